// round 9
// baseline (speedup 1.0000x reference)
#include <cuda_runtime.h>
#include <math.h>

#define B_   2
#define N_   16384
#define M_   4096
#define KG_  32
#define FULL 0xffffffffu

#define G_    8                 // FPS CTAs per batch
#define TC    512               // threads per FPS CTA
#define CHUNK (N_ / G_)         // 2048 points per CTA
#define PPTC  (CHUNK / TC)      // 4 points per thread
#define NW    (TC / 32)         // 16 warps

typedef unsigned long long ull;

// ------------------------- device scratch (no allocs) ------------------------
__device__ __align__(16) static float4 g_pk[B_][N_];   // x,y,z,|p|^2
__device__ static float g_xs[B_][N_];
__device__ static float g_ys[B_][N_];
__device__ static float g_zs[B_][N_];
__device__ static int   g_fps[B_][M_];
__device__ static float g_FL[B_ * M_ * 64];
__device__ static float g_thr;
__device__ __align__(128) static ull g_slot[B_][G_];   // (val,~idx,tag) keys; one line/batch

// ------------------------- f32x2 + memory-order helpers ----------------------
__device__ __forceinline__ ull pack2(float a, float b) {
    ull r; asm("mov.b64 %0, {%1, %2};" : "=l"(r) : "f"(a), "f"(b)); return r;
}
__device__ __forceinline__ void unpack2(ull v, float& a, float& b) {
    asm("mov.b64 {%0, %1}, %2;" : "=f"(a), "=f"(b) : "l"(v));
}
__device__ __forceinline__ ull addx2(ull a, ull b) {
    ull r; asm("add.rn.f32x2 %0, %1, %2;" : "=l"(r) : "l"(a), "l"(b)); return r;
}
__device__ __forceinline__ ull mulx2(ull a, ull b) {
    ull r; asm("mul.rn.f32x2 %0, %1, %2;" : "=l"(r) : "l"(a), "l"(b)); return r;
}
__device__ __forceinline__ void st_rel_u64(ull* p, ull v) {
    asm volatile("st.release.gpu.u64 [%0], %1;" :: "l"(p), "l"(v) : "memory");
}
__device__ __forceinline__ ull ld_acq_u64(ull* p) {
    ull v; asm volatile("ld.acquire.gpu.u64 %0, [%1];" : "=l"(v) : "l"(p) : "memory");
    return v;
}

// ------------------------- K1: SoA prep + norms ------------------------------
__global__ void k_prep(const float* __restrict__ xyz) {
    int i = blockIdx.x * blockDim.x + threadIdx.x;
    if (i >= B_ * N_) return;
    int b = i / N_, p = i - b * N_;
    float x = xyz[3 * i + 0], y = xyz[3 * i + 1], z = xyz[3 * i + 2];
    // matches jnp.sum(b*b,-1): ((x*x + y*y) + z*z), no fma contraction
    float n = __fadd_rn(__fadd_rn(__fmul_rn(x, x), __fmul_rn(y, y)), __fmul_rn(z, z));
    g_xs[b][p] = x; g_ys[b][p] = y; g_zs[b][p] = z;
    g_pk[b][p] = make_float4(x, y, z, n);
}

// ------------------------- K2: threshold net (constant input) ----------------
__global__ void k_thr(const float* __restrict__ tw1, const float* __restrict__ tb1,
                      const float* __restrict__ tw2, const float* __restrict__ tb2,
                      const float* __restrict__ tw3, const float* __restrict__ tb3) {
    __shared__ float t1s[64], t2s[64];
    int o = threadIdx.x;
    float dens = (float)(64.0 / (4.0 / 3.0 * 3.14159));   // radius 1.0
    t1s[o] = fmaxf(fmaf(dens, tw1[o], tb1[o]), 0.f);
    __syncthreads();
    float acc = tb2[o];
    #pragma unroll 8
    for (int i = 0; i < 64; i++) acc = fmaf(t1s[i], tw2[o * 64 + i], acc);
    t2s[o] = fmaxf(acc, 0.f);
    __syncthreads();
    if (o == 0) {
        float a = tb3[0];
        for (int i = 0; i < 64; i++) a = fmaf(t2s[i], tw3[i], a);
        float sg = 1.f / (1.f + expf(-a));
        g_thr = 20.f + 40.f * sg;
    }
}

// ------------------------- K3: cooperative multi-CTA FPS ---------------------
// 8 CTAs per batch (16 total; 192KB smem -> 1 CTA/SM; 16 << 148 SMs so all
// co-resident in wave 1 — spin-sync is starvation-free).
// Each CTA owns 2048 register-resident points; full coords in SMEM for the
// (broadcast) centroid lookup. Cross-CTA argmax via release/acquire u64 keys:
//   key = valbits<<32 | (0xFFFFFF - idx)<<8 | (it+1)&0xFF
// u64 max == (max value, then min index) — exact jnp.argmax semantics.
// Tag protocol: a slot only ever holds tag (it)&0xFF or (it+1)&0xFF — always
// distinct; stale cross-replay tag is 0 vs first expected 1.
__global__ __launch_bounds__(TC, 1) void k_fps() {
    extern __shared__ float sm[];
    float* sxs = sm;
    float* sys = sm + N_;
    float* szs = sm + 2 * N_;
    __shared__ unsigned s_val[NW];
    __shared__ int      s_idx[NW];
    __shared__ int      s_far;

    int b = blockIdx.x / G_;
    int g = blockIdx.x - b * G_;
    int tid = threadIdx.x;
    int lane = tid & 31, wid = tid >> 5;
    int base = g * CHUNK;

    for (int i = tid; i < N_; i += TC) {
        sxs[i] = g_xs[b][i]; sys[i] = g_ys[b][i]; szs[i] = g_zs[b][i];
    }
    __syncthreads();

    // register points: local p = tid + k*TC (k=0..3), global = base + p
    ull X[PPTC / 2], Y[PPTC / 2], Z[PPTC / 2];
    float dist[PPTC];
    #pragma unroll
    for (int j = 0; j < PPTC / 2; j++) {
        int p0 = base + tid + (2 * j) * TC;
        int p1 = base + tid + (2 * j + 1) * TC;
        X[j] = pack2(sxs[p0], sxs[p1]);
        Y[j] = pack2(sys[p0], sys[p1]);
        Z[j] = pack2(szs[p0], szs[p1]);
    }
    #pragma unroll
    for (int k = 0; k < PPTC; k++) dist[k] = 1e10f;

    int far = 0;
    for (int it = 0; it < M_; ++it) {
        if (g == 0 && tid == 0) g_fps[b][it] = far;
        float cx = sxs[far], cy = sys[far], cz = szs[far];
        ull ncx = pack2(-cx, -cx), ncy = pack2(-cy, -cy), ncz = pack2(-cz, -cz);
        float bv = -1.0f; int bi = 0x7fffffff;
        #pragma unroll
        for (int j = 0; j < PPTC / 2; j++) {
            // x + (-c) == x - c exactly; ((dx*dx + dy*dy) + dz*dz) rn order
            ull dx = addx2(X[j], ncx);
            ull dy = addx2(Y[j], ncy);
            ull dz = addx2(Z[j], ncz);
            ull d2 = addx2(addx2(mulx2(dx, dx), mulx2(dy, dy)), mulx2(dz, dz));
            float d0, d1; unpack2(d2, d0, d1);
            float n0 = fminf(dist[2 * j], d0);     dist[2 * j] = n0;
            if (n0 > bv) { bv = n0; bi = tid + (2 * j) * TC; }   // p asc: first max
            float n1 = fminf(dist[2 * j + 1], d1); dist[2 * j + 1] = n1;
            if (n1 > bv) { bv = n1; bi = tid + (2 * j + 1) * TC; }
        }
        // warp argmax (nonneg float bits monotonic; ties -> min index)
        unsigned vb = __float_as_uint(bv);
        unsigned wmax = __reduce_max_sync(FULL, vb);
        unsigned ci = (vb == wmax) ? (unsigned)bi : 0xffffffffu;
        unsigned wix = __reduce_min_sync(FULL, ci);
        if (lane == 0) { s_val[wid] = wmax; s_idx[wid] = (int)wix; }
        __syncthreads();
        if (wid == 0) {
            unsigned v2 = (lane < NW) ? s_val[lane] : 0u;
            unsigned i2 = (lane < NW) ? (unsigned)s_idx[lane] : 0xffffffffu;
            unsigned m2 = __reduce_max_sync(FULL, v2);
            unsigned c2 = (v2 == m2) ? i2 : 0xffffffffu;
            unsigned f2 = __reduce_min_sync(FULL, c2);
            unsigned tag = (unsigned)((it + 1) & 0xFF);
            if (lane == 0) {
                int gidx = base + (int)f2;
                ull key = ((ull)m2 << 32)
                        | ((ull)((0xFFFFFFu - (unsigned)gidx) & 0xFFFFFFu) << 8)
                        | (ull)tag;
                st_rel_u64(&g_slot[b][g], key);
            }
            ull k = 0;
            if (lane < G_) {
                k = ld_acq_u64(&g_slot[b][lane]);
                while ((unsigned)(k & 0xFFu) != tag) {
                    __nanosleep(32);
                    k = ld_acq_u64(&g_slot[b][lane]);
                }
            }
            #pragma unroll
            for (int s = 16; s; s >>= 1) {          // lanes>=8 carry 0 (never wins)
                ull o = __shfl_xor_sync(FULL, k, s);
                if (o > k) k = o;
            }
            if (lane == 0)
                s_far = (int)(0xFFFFFFu - (unsigned)((k >> 8) & 0xFFFFFFu));
        }
        __syncthreads();
        far = s_far;
    }
}

// ------------------------- K4: kNN top-32 + shared MLP + masked max ----------
// 256 threads = 8 warps; warp = one centroid; SMEM point tile shared by block.
__global__ __launch_bounds__(256) void k_knn(
    const float* __restrict__ w1, const float* __restrict__ s1, const float* __restrict__ b1,
    const float* __restrict__ w2, const float* __restrict__ s2, const float* __restrict__ b2,
    const float* __restrict__ w3, const float* __restrict__ s3, const float* __restrict__ b3) {

    __shared__ float4 s_tile[2048];                       // 32 KB
    __shared__ float s_w1[96],  s_s1[32], s_b1[32];
    __shared__ float s_w2[1024], s_s2[32], s_b2[32];
    __shared__ float s_w3[2048], s_s3[64], s_b3[64];

    int tid = threadIdx.x;
    int lane = tid & 31, warp = tid >> 5;

    for (int i = tid; i < 96;   i += 256) s_w1[i] = w1[i];
    for (int i = tid; i < 1024; i += 256) s_w2[i] = w2[i];
    for (int i = tid; i < 2048; i += 256) s_w3[i] = w3[i];
    if (tid < 32) { s_s1[tid] = s1[tid]; s_b1[tid] = b1[tid];
                    s_s2[tid] = s2[tid]; s_b2[tid] = b2[tid]; }
    if (tid < 64) { s_s3[tid] = s3[tid]; s_b3[tid] = b3[tid]; }

    int b = blockIdx.x >> 9;                               // 512 blocks / batch
    int m = ((blockIdx.x & 511) << 3) + warp;
    int cidx = g_fps[b][m];
    float4 c = g_pk[b][cidx];

    const float INFP = __int_as_float(0x7f800000);
    float curmax = INFP;
    float candD  = INFP;
    // lane-unique sentinels > any real index so evict-max-(value,index) is
    // deterministic while the set is unfull
    int   candI  = 0x7fffff00 | lane;

    for (int tile = 0; tile < 8; tile++) {
        __syncthreads();
        for (int i = tid; i < 2048; i += 256) s_tile[i] = g_pk[b][(tile << 11) + i];
        __syncthreads();
        for (int t = 0; t < 64; t++) {
            float4 p = s_tile[(t << 5) + lane];
            int pidx = (tile << 11) + (t << 5) + lane;
            // reference cdist: (an + bn) - 2*dot, no fma; clamp at 0
            float dot = __fadd_rn(__fadd_rn(__fmul_rn(c.x, p.x), __fmul_rn(c.y, p.y)),
                                  __fmul_rn(c.z, p.z));
            float d2 = fmaxf(__fsub_rn(__fadd_rn(c.w, p.w), __fmul_rn(2.f, dot)), 0.f);
            unsigned bal = __ballot_sync(FULL, d2 < curmax);
            while (bal) {
                int src = __ffs(bal) - 1;
                bal &= bal - 1;
                float dn = __shfl_sync(FULL, d2, src);
                int   in = __shfl_sync(FULL, pidx, src);
                if (dn < curmax) {               // strict < : stable top_k ties
                    unsigned db = __float_as_uint(candD);
                    unsigned mb = __reduce_max_sync(FULL, db);
                    int ei = (db == mb) ? candI : -1;
                    int me = __reduce_max_sync(FULL, ei);
                    if (db == mb && candI == me) { candD = dn; candI = in; }
                    curmax = __uint_as_float(
                        __reduce_max_sync(FULL, __float_as_uint(candD)));
                }
            }
        }
    }

    // lane = neighbor k. Mask exactly as reference: sqrt(max(d2,0)) <= 0.8
    bool msk = (__fsqrt_rn(candD) <= 0.8f);
    float4 np = g_pk[b][candI];
    float gx = __fsub_rn(np.x, c.x);
    float gy = __fsub_rn(np.y, c.y);
    float gz = __fsub_rn(np.z, c.z);

    float h1[32];
    #pragma unroll
    for (int o = 0; o < 32; o++) {
        float a = __fmul_rn(gx, s_w1[3 * o]);
        a = fmaf(gy, s_w1[3 * o + 1], a);
        a = fmaf(gz, s_w1[3 * o + 2], a);
        h1[o] = fmaxf(fmaf(a, s_s1[o], s_b1[o]), 0.f);
    }
    float h2[32];
    #pragma unroll
    for (int o = 0; o < 32; o++) {
        float acc = 0.f;
        #pragma unroll
        for (int i = 0; i < 32; i++) acc = fmaf(h1[i], s_w2[(o << 5) + i], acc);
        h2[o] = fmaxf(fmaf(acc, s_s2[o], s_b2[o]), 0.f);
    }
    const float NINF = __int_as_float(0xff800000);
    float* outFL = &g_FL[((b << 12) + m) * 64];
    for (int o = 0; o < 64; o++) {
        float acc = 0.f;
        #pragma unroll
        for (int i = 0; i < 32; i++) acc = fmaf(h2[i], s_w3[(o << 5) + i], acc);
        float v = fmaxf(fmaf(acc, s_s3[o], s_b3[o]), 0.f);
        if (!msk) v = NINF;
        #pragma unroll
        for (int s = 16; s; s >>= 1) v = fmaxf(v, __shfl_xor_sync(FULL, v, s));
        if (lane == 0) outFL[o] = v;
    }
}

// ------------------------- K5: DAM fusion ------------------------------------
__global__ __launch_bounds__(64) void k_fuse(
    const float* __restrict__ xyz, const float* __restrict__ pts_cam,
    const float* __restrict__ FI,
    const float* __restrict__ gw_raw, const float* __restrict__ gb_raw,
    const float* __restrict__ gw_img, const float* __restrict__ gb_img,
    const float* __restrict__ gw_lid, const float* __restrict__ gb_lid,
    const float* __restrict__ uw, const float* __restrict__ ub,
    const float* __restrict__ vw, const float* __restrict__ vb,
    float* __restrict__ out) {

    __shared__ float sFI[64], sFL[64], sPI[64], sPV[64], sW[2];
    int h = threadIdx.x;
    int g = blockIdx.x;
    int b = g >> 12, m = g & 4095;
    int idx = g_fps[b][m];

    sFI[h] = FI[((b << 6) + h) * N_ + idx];
    sFL[h] = g_FL[((b << 12) + m) * 64 + h];
    __syncthreads();

    float x0 = xyz[(b * N_ + idx) * 3 + 0];
    float x1 = xyz[(b * N_ + idx) * 3 + 1];
    float x2 = xyz[(b * N_ + idx) * 3 + 2];

    float fr = gb_raw[h];
    fr = fmaf(x0, gw_raw[3 * h + 0], fr);
    fr = fmaf(x1, gw_raw[3 * h + 1], fr);
    fr = fmaf(x2, gw_raw[3 * h + 2], fr);
    fr = fmaxf(fr, 0.f);

    float fi = gb_img[h], fl = gb_lid[h];
    #pragma unroll 8
    for (int i = 0; i < 64; i++) {
        fi = fmaf(sFI[i], gw_img[(h << 6) + i], fi);
        fl = fmaf(sFL[i], gw_lid[(h << 6) + i], fl);
    }
    fi = fmaxf(fi, 0.f);
    fl = fmaxf(fl, 0.f);

    float s = tanhf(fr + fi + fl);
    sPI[h] = s * uw[h];
    sPV[h] = s * vw[h];
    __syncthreads();
    if (h == 0) {
        float aI = ub[0], aV = vb[0];
        for (int i = 0; i < 64; i++) { aI += sPI[i]; aV += sPV[i]; }
        sW[0] = 1.f / (1.f + expf(-aI));
        sW[1] = 1.f / (1.f + expf(-aV));
    }
    __syncthreads();
    float wI = sW[0], wL = sW[1];

    float z = pts_cam[(b * N_ + idx) * 3 + 2];
    bool near = (z <= g_thr);
    float o1 = near ? sFL[h] : sFI[h];
    float o2 = near ? sFI[h] * wI : sFL[h] * wL;
    out[((b << 7) + h) * M_ + m]        = o1;
    out[((b << 7) + 64 + h) * M_ + m]   = o2;
}

// ------------------------- launch --------------------------------------------
extern "C" void kernel_launch(void* const* d_in, const int* in_sizes, int n_in,
                              void* d_out, int out_size) {
    const float* xyz     = (const float*)d_in[0];
    const float* pts_cam = (const float*)d_in[1];
    const float* FI      = (const float*)d_in[2];
    const float* w1 = (const float*)d_in[3];
    const float* s1 = (const float*)d_in[4];
    const float* b1 = (const float*)d_in[5];
    const float* w2 = (const float*)d_in[6];
    const float* s2 = (const float*)d_in[7];
    const float* b2 = (const float*)d_in[8];
    const float* w3 = (const float*)d_in[9];
    const float* s3 = (const float*)d_in[10];
    const float* b3 = (const float*)d_in[11];
    const float* tw1 = (const float*)d_in[12];
    const float* tb1 = (const float*)d_in[13];
    const float* tw2 = (const float*)d_in[14];
    const float* tb2 = (const float*)d_in[15];
    const float* tw3 = (const float*)d_in[16];
    const float* tb3 = (const float*)d_in[17];
    const float* gw_raw = (const float*)d_in[18];
    const float* gb_raw = (const float*)d_in[19];
    const float* gw_img = (const float*)d_in[20];
    const float* gb_img = (const float*)d_in[21];
    const float* gw_lid = (const float*)d_in[22];
    const float* gb_lid = (const float*)d_in[23];
    const float* uw = (const float*)d_in[24];
    const float* ub = (const float*)d_in[25];
    const float* vw = (const float*)d_in[26];
    const float* vb = (const float*)d_in[27];
    float* out = (float*)d_out;

    k_prep<<<(B_ * N_ + 255) / 256, 256>>>(xyz);
    k_thr<<<1, 64>>>(tw1, tb1, tw2, tb2, tw3, tb3);

    cudaFuncSetAttribute(k_fps, cudaFuncAttributeMaxDynamicSharedMemorySize,
                         3 * N_ * (int)sizeof(float));
    k_fps<<<B_ * G_, TC, 3 * N_ * sizeof(float)>>>();

    k_knn<<<(B_ * M_) / 8, 256>>>(w1, s1, b1, w2, s2, b2, w3, s3, b3);
    k_fuse<<<B_ * M_, 64>>>(xyz, pts_cam, FI,
                            gw_raw, gb_raw, gw_img, gb_img, gw_lid, gb_lid,
                            uw, ub, vw, vb, out);
}

// round 10
// speedup vs baseline: 1.9042x; 1.9042x over previous
#include <cuda_runtime.h>
#include <math.h>

#define B_   2
#define N_   16384
#define M_   4096
#define KG_  32
#define FULL 0xffffffffu

#define G_    8                 // FPS CTAs per cluster (one cluster per batch)
#define TCC   256               // threads per FPS CTA
#define CHUNK (N_ / G_)         // 2048 points per CTA
#define PPT8  (CHUNK / TCC)     // 8 points per thread
#define PR    (PPT8 / 2)        // 4 f32x2 pairs
#define NWC   (TCC / 32)        // 8 warps

typedef unsigned long long ull;

// ------------------------- device scratch (no allocs) ------------------------
__device__ __align__(16) static float4 g_pk[B_][N_];   // x,y,z,|p|^2
__device__ static float g_xs[B_][N_];
__device__ static float g_ys[B_][N_];
__device__ static float g_zs[B_][N_];
__device__ static int   g_fps[B_][M_];
__device__ static float g_FL[B_ * M_ * 64];
__device__ static float g_thr;

// ------------------------- f32x2 helpers -------------------------------------
__device__ __forceinline__ ull pack2(float a, float b) {
    ull r; asm("mov.b64 %0, {%1, %2};" : "=l"(r) : "f"(a), "f"(b)); return r;
}
__device__ __forceinline__ void unpack2(ull v, float& a, float& b) {
    asm("mov.b64 {%0, %1}, %2;" : "=f"(a), "=f"(b) : "l"(v));
}
__device__ __forceinline__ ull addx2(ull a, ull b) {
    ull r; asm("add.rn.f32x2 %0, %1, %2;" : "=l"(r) : "l"(a), "l"(b)); return r;
}
__device__ __forceinline__ ull mulx2(ull a, ull b) {
    ull r; asm("mul.rn.f32x2 %0, %1, %2;" : "=l"(r) : "l"(a), "l"(b)); return r;
}

// ------------------------- DSMEM / cluster helpers ---------------------------
__device__ __forceinline__ unsigned smem_u32(const void* p) {
    return (unsigned)__cvta_generic_to_shared(p);
}
__device__ __forceinline__ unsigned mapa_rank(unsigned laddr, unsigned rank) {
    unsigned r;
    asm("mapa.shared::cluster.u32 %0, %1, %2;" : "=r"(r) : "r"(laddr), "r"(rank));
    return r;
}
__device__ __forceinline__ void st_dsm(unsigned a, ull v) {
    asm volatile("st.shared::cluster.u64 [%0], %1;" :: "r"(a), "l"(v) : "memory");
}
__device__ __forceinline__ void st_rel_dsm(unsigned a, ull v) {
    asm volatile("st.release.cluster.shared::cluster.u64 [%0], %1;"
                 :: "r"(a), "l"(v) : "memory");
}
__device__ __forceinline__ ull ld_acq_sm(unsigned a) {
    ull v;
    asm volatile("ld.acquire.cluster.shared.u64 %0, [%1];" : "=l"(v) : "r"(a) : "memory");
    return v;
}
__device__ __forceinline__ ull ld_sm(unsigned a) {
    ull v; asm volatile("ld.shared.u64 %0, [%1];" : "=l"(v) : "r"(a) : "memory");
    return v;
}
#define CLUSTER_SYNC() do { \
    asm volatile("barrier.cluster.arrive.aligned;" ::: "memory"); \
    asm volatile("barrier.cluster.wait.aligned;"   ::: "memory"); } while (0)

// ------------------------- K1: SoA prep + norms ------------------------------
__global__ void k_prep(const float* __restrict__ xyz) {
    int i = blockIdx.x * blockDim.x + threadIdx.x;
    if (i >= B_ * N_) return;
    int b = i / N_, p = i - b * N_;
    float x = xyz[3 * i + 0], y = xyz[3 * i + 1], z = xyz[3 * i + 2];
    // matches jnp.sum(b*b,-1): ((x*x + y*y) + z*z), no fma contraction
    float n = __fadd_rn(__fadd_rn(__fmul_rn(x, x), __fmul_rn(y, y)), __fmul_rn(z, z));
    g_xs[b][p] = x; g_ys[b][p] = y; g_zs[b][p] = z;
    g_pk[b][p] = make_float4(x, y, z, n);
}

// ------------------------- K2: threshold net (constant input) ----------------
__global__ void k_thr(const float* __restrict__ tw1, const float* __restrict__ tb1,
                      const float* __restrict__ tw2, const float* __restrict__ tb2,
                      const float* __restrict__ tw3, const float* __restrict__ tb3) {
    __shared__ float t1s[64], t2s[64];
    int o = threadIdx.x;
    float dens = (float)(64.0 / (4.0 / 3.0 * 3.14159));   // radius 1.0
    t1s[o] = fmaxf(fmaf(dens, tw1[o], tb1[o]), 0.f);
    __syncthreads();
    float acc = tb2[o];
    #pragma unroll 8
    for (int i = 0; i < 64; i++) acc = fmaf(t1s[i], tw2[o * 64 + i], acc);
    t2s[o] = fmaxf(acc, 0.f);
    __syncthreads();
    if (o == 0) {
        float a = tb3[0];
        for (int i = 0; i < 64; i++) a = fmaf(t2s[i], tw3[i], a);
        float sg = 1.f / (1.f + expf(-a));
        g_thr = 20.f + 40.f * sg;
    }
}

// ------------------------- K3: cluster-cooperative FPS -----------------------
// One 8-CTA cluster per batch. Each CTA owns 2048 points (registers, f32x2).
// Cross-CTA argmax through DSMEM mailboxes with tag-in-low-byte keys:
//   key = valbits<<32 | (0xFFFFFF - gidx)<<8 | (it+1)&0xFF
// u64 max == (max value, then min index) — exact jnp.argmax semantics.
// Winner COORDS travel with the key, so no CTA needs the full point set.
__global__ __launch_bounds__(TCC, 1) __cluster_dims__(G_, 1, 1)
void k_fps() {
    __shared__ float sxs[CHUNK], sys[CHUNK], szs[CHUNK];    // 24 KB
    __shared__ ull gth[G_ * 4];   // rank0 gather: [g*4+0]=xy [.+1]=z [.+2]=key
    __shared__ ull res[4];        // broadcast:    [0]=xy [1]=z [2]=key
    __shared__ unsigned s_val[NWC];
    __shared__ unsigned s_idx[NWC];

    int b    = blockIdx.x >> 3;          // cluster id (contiguous blocks)
    int g    = blockIdx.x & 7;           // rank in cluster
    int tid  = threadIdx.x;
    int lane = tid & 31, wid = tid >> 5;
    unsigned base = (unsigned)g * CHUNK;

    // zero mailboxes (tag bytes) before any cross-CTA traffic
    if (tid < G_ * 4) gth[tid] = 0;
    if (tid < 4)      res[tid] = 0;

    for (int i = tid; i < CHUNK; i += TCC) {
        sxs[i] = g_xs[b][base + i];
        sys[i] = g_ys[b][base + i];
        szs[i] = g_zs[b][base + i];
    }
    __syncthreads();
    CLUSTER_SYNC();                      // mailbox zeroing visible cluster-wide

    // register-resident points: local p = tid + k*TCC, k = 0..7, packed pairs
    ull X[PR], Y[PR], Z[PR];
    float dist[PPT8];
    #pragma unroll
    for (int j = 0; j < PR; j++) {
        int p0 = tid + (2 * j) * TCC, p1 = tid + (2 * j + 1) * TCC;
        X[j] = pack2(sxs[p0], sxs[p1]);
        Y[j] = pack2(sys[p0], sys[p1]);
        Z[j] = pack2(szs[p0], szs[p1]);
    }
    #pragma unroll
    for (int k = 0; k < PPT8; k++) dist[k] = 1e10f;

    // hoisted DSMEM addresses
    unsigned a_gxy = 0, a_gz = 0, a_gkey = 0;
    if (wid == 0 && lane == 0) {
        a_gxy  = mapa_rank(smem_u32(&gth[g * 4 + 0]), 0);
        a_gz   = mapa_rank(smem_u32(&gth[g * 4 + 1]), 0);
        a_gkey = mapa_rank(smem_u32(&gth[g * 4 + 2]), 0);
    }
    unsigned a_rxy = 0, a_rz = 0, a_rkey = 0, a_lgk = 0;
    if (g == 0 && wid == 0 && lane < G_) {
        a_rxy  = mapa_rank(smem_u32(&res[0]), (unsigned)lane);
        a_rz   = mapa_rank(smem_u32(&res[1]), (unsigned)lane);
        a_rkey = mapa_rank(smem_u32(&res[2]), (unsigned)lane);
        a_lgk  = smem_u32(&gth[lane * 4 + 2]);
    }
    unsigned my_rkey = smem_u32(&res[2]);
    unsigned my_rxy  = smem_u32(&res[0]);
    unsigned my_rz   = smem_u32(&res[1]);

    float cx = g_xs[b][0], cy = g_ys[b][0], cz = g_zs[b][0];
    unsigned fidx = 0;

    for (int it = 0; it < M_; ++it) {
        if (g == 0 && tid == 0) g_fps[b][it] = (int)fidx;
        if (it == M_ - 1) break;                       // last centroid unused
        unsigned tag = (unsigned)((it + 1) & 0xFF);

        ull ncx = pack2(-cx, -cx), ncy = pack2(-cy, -cy), ncz = pack2(-cz, -cz);
        float bv = -1.0f; unsigned bi = 0xffffffffu;
        #pragma unroll
        for (int j = 0; j < PR; j++) {
            // x + (-c) == x - c exactly; ((dx*dx + dy*dy) + dz*dz) rn order
            ull dx = addx2(X[j], ncx);
            ull dy = addx2(Y[j], ncy);
            ull dz = addx2(Z[j], ncz);
            ull d2 = addx2(addx2(mulx2(dx, dx), mulx2(dy, dy)), mulx2(dz, dz));
            float d0, d1; unpack2(d2, d0, d1);
            float n0 = fminf(dist[2 * j], d0);     dist[2 * j] = n0;
            if (n0 > bv) { bv = n0; bi = tid + (2 * j) * TCC; }   // p asc: first max
            float n1 = fminf(dist[2 * j + 1], d1); dist[2 * j + 1] = n1;
            if (n1 > bv) { bv = n1; bi = tid + (2 * j + 1) * TCC; }
        }
        // warp argmax (nonneg float bits monotonic; ties -> min local idx)
        unsigned vb = __float_as_uint(bv);
        unsigned wmax = __reduce_max_sync(FULL, vb);
        unsigned ci = (vb == wmax) ? bi : 0xffffffffu;
        unsigned wix = __reduce_min_sync(FULL, ci);
        if (lane == 0) { s_val[wid] = wmax; s_idx[wid] = wix; }
        __syncthreads();

        if (wid == 0) {
            unsigned v2 = (lane < NWC) ? s_val[lane] : 0u;
            unsigned i2 = (lane < NWC) ? s_idx[lane] : 0xffffffffu;
            unsigned m2 = __reduce_max_sync(FULL, v2);
            unsigned c2 = (v2 == m2) ? i2 : 0xffffffffu;
            unsigned f2 = __reduce_min_sync(FULL, c2);
            if (lane == 0) {
                unsigned gidx = base + f2;
                ull key = ((ull)m2 << 32)
                        | ((ull)((0xFFFFFFu - gidx) & 0xFFFFFFu) << 8)
                        | (ull)tag;
                st_dsm(a_gxy, pack2(sxs[f2], sys[f2]));
                st_dsm(a_gz,  pack2(szs[f2], 0.f));
                st_rel_dsm(a_gkey, key);                // tag word last, release
            }
            if (g == 0 && lane < G_) {
                ull k = ld_acq_sm(a_lgk);
                while ((unsigned)(k & 0xFFu) != tag) k = ld_acq_sm(a_lgk);
                ull xy = ld_sm(smem_u32(&gth[lane * 4 + 0]));
                ull zz = ld_sm(smem_u32(&gth[lane * 4 + 1]));
                #pragma unroll
                for (int s = 4; s; s >>= 1) {           // 8-lane xor argmax
                    ull ok  = __shfl_xor_sync(0xFFu, k,  s);
                    ull oxy = __shfl_xor_sync(0xFFu, xy, s);
                    ull ozz = __shfl_xor_sync(0xFFu, zz, s);
                    if (ok > k) { k = ok; xy = oxy; zz = ozz; }
                }
                // every lane holds the winner; lane -> CTA rank=lane mailbox
                st_dsm(a_rxy, xy);
                st_dsm(a_rz,  zz);
                st_rel_dsm(a_rkey, k);
            }
        }
        // all threads self-serve the broadcast from local SMEM (cheap LDS poll)
        ull k = ld_acq_sm(my_rkey);
        while ((unsigned)(k & 0xFFu) != tag) k = ld_acq_sm(my_rkey);
        ull xy = ld_sm(my_rxy);
        ull zz = ld_sm(my_rz);
        float zdum;
        unpack2(xy, cx, cy);
        unpack2(zz, cz, zdum);
        fidx = 0xFFFFFFu - (unsigned)((k >> 8) & 0xFFFFFFu);
    }
    CLUSTER_SYNC();                      // no CTA exits with remote stores in flight
}

// ------------------------- K4: kNN top-32 + shared MLP + masked max ----------
// 256 threads = 8 warps; warp = one centroid; SMEM point tile shared by block.
__global__ __launch_bounds__(256) void k_knn(
    const float* __restrict__ w1, const float* __restrict__ s1, const float* __restrict__ b1,
    const float* __restrict__ w2, const float* __restrict__ s2, const float* __restrict__ b2,
    const float* __restrict__ w3, const float* __restrict__ s3, const float* __restrict__ b3) {

    __shared__ float4 s_tile[2048];                       // 32 KB
    __shared__ float s_w1[96],  s_s1[32], s_b1[32];
    __shared__ float s_w2[1024], s_s2[32], s_b2[32];
    __shared__ float s_w3[2048], s_s3[64], s_b3[64];

    int tid = threadIdx.x;
    int lane = tid & 31, warp = tid >> 5;

    for (int i = tid; i < 96;   i += 256) s_w1[i] = w1[i];
    for (int i = tid; i < 1024; i += 256) s_w2[i] = w2[i];
    for (int i = tid; i < 2048; i += 256) s_w3[i] = w3[i];
    if (tid < 32) { s_s1[tid] = s1[tid]; s_b1[tid] = b1[tid];
                    s_s2[tid] = s2[tid]; s_b2[tid] = b2[tid]; }
    if (tid < 64) { s_s3[tid] = s3[tid]; s_b3[tid] = b3[tid]; }

    int b = blockIdx.x >> 9;                               // 512 blocks / batch
    int m = ((blockIdx.x & 511) << 3) + warp;
    int cidx = g_fps[b][m];
    float4 c = g_pk[b][cidx];

    const float INFP = __int_as_float(0x7f800000);
    float curmax = INFP;
    float candD  = INFP;
    // lane-unique sentinels > any real index so evict-max-(value,index) is
    // deterministic while the set is unfull
    int   candI  = 0x7fffff00 | lane;

    for (int tile = 0; tile < 8; tile++) {
        __syncthreads();
        for (int i = tid; i < 2048; i += 256) s_tile[i] = g_pk[b][(tile << 11) + i];
        __syncthreads();
        for (int t = 0; t < 64; t++) {
            float4 p = s_tile[(t << 5) + lane];
            int pidx = (tile << 11) + (t << 5) + lane;
            // reference cdist: (an + bn) - 2*dot, no fma; clamp at 0
            float dot = __fadd_rn(__fadd_rn(__fmul_rn(c.x, p.x), __fmul_rn(c.y, p.y)),
                                  __fmul_rn(c.z, p.z));
            float d2 = fmaxf(__fsub_rn(__fadd_rn(c.w, p.w), __fmul_rn(2.f, dot)), 0.f);
            unsigned bal = __ballot_sync(FULL, d2 < curmax);
            while (bal) {
                int src = __ffs(bal) - 1;
                bal &= bal - 1;
                float dn = __shfl_sync(FULL, d2, src);
                int   in = __shfl_sync(FULL, pidx, src);
                if (dn < curmax) {               // strict < : stable top_k ties
                    unsigned db = __float_as_uint(candD);
                    unsigned mb = __reduce_max_sync(FULL, db);
                    int ei = (db == mb) ? candI : -1;
                    int me = __reduce_max_sync(FULL, ei);
                    if (db == mb && candI == me) { candD = dn; candI = in; }
                    curmax = __uint_as_float(
                        __reduce_max_sync(FULL, __float_as_uint(candD)));
                }
            }
        }
    }

    // lane = neighbor k. Mask exactly as reference: sqrt(max(d2,0)) <= 0.8
    bool msk = (__fsqrt_rn(candD) <= 0.8f);
    float4 np = g_pk[b][candI];
    float gx = __fsub_rn(np.x, c.x);
    float gy = __fsub_rn(np.y, c.y);
    float gz = __fsub_rn(np.z, c.z);

    float h1[32];
    #pragma unroll
    for (int o = 0; o < 32; o++) {
        float a = __fmul_rn(gx, s_w1[3 * o]);
        a = fmaf(gy, s_w1[3 * o + 1], a);
        a = fmaf(gz, s_w1[3 * o + 2], a);
        h1[o] = fmaxf(fmaf(a, s_s1[o], s_b1[o]), 0.f);
    }
    float h2[32];
    #pragma unroll
    for (int o = 0; o < 32; o++) {
        float acc = 0.f;
        #pragma unroll
        for (int i = 0; i < 32; i++) acc = fmaf(h1[i], s_w2[(o << 5) + i], acc);
        h2[o] = fmaxf(fmaf(acc, s_s2[o], s_b2[o]), 0.f);
    }
    const float NINF = __int_as_float(0xff800000);
    float* outFL = &g_FL[((b << 12) + m) * 64];
    for (int o = 0; o < 64; o++) {
        float acc = 0.f;
        #pragma unroll
        for (int i = 0; i < 32; i++) acc = fmaf(h2[i], s_w3[(o << 5) + i], acc);
        float v = fmaxf(fmaf(acc, s_s3[o], s_b3[o]), 0.f);
        if (!msk) v = NINF;
        #pragma unroll
        for (int s = 16; s; s >>= 1) v = fmaxf(v, __shfl_xor_sync(FULL, v, s));
        if (lane == 0) outFL[o] = v;
    }
}

// ------------------------- K5: DAM fusion ------------------------------------
__global__ __launch_bounds__(64) void k_fuse(
    const float* __restrict__ xyz, const float* __restrict__ pts_cam,
    const float* __restrict__ FI,
    const float* __restrict__ gw_raw, const float* __restrict__ gb_raw,
    const float* __restrict__ gw_img, const float* __restrict__ gb_img,
    const float* __restrict__ gw_lid, const float* __restrict__ gb_lid,
    const float* __restrict__ uw, const float* __restrict__ ub,
    const float* __restrict__ vw, const float* __restrict__ vb,
    float* __restrict__ out) {

    __shared__ float sFI[64], sFL[64], sPI[64], sPV[64], sW[2];
    int h = threadIdx.x;
    int g = blockIdx.x;
    int b = g >> 12, m = g & 4095;
    int idx = g_fps[b][m];

    sFI[h] = FI[((b << 6) + h) * N_ + idx];
    sFL[h] = g_FL[((b << 12) + m) * 64 + h];
    __syncthreads();

    float x0 = xyz[(b * N_ + idx) * 3 + 0];
    float x1 = xyz[(b * N_ + idx) * 3 + 1];
    float x2 = xyz[(b * N_ + idx) * 3 + 2];

    float fr = gb_raw[h];
    fr = fmaf(x0, gw_raw[3 * h + 0], fr);
    fr = fmaf(x1, gw_raw[3 * h + 1], fr);
    fr = fmaf(x2, gw_raw[3 * h + 2], fr);
    fr = fmaxf(fr, 0.f);

    float fi = gb_img[h], fl = gb_lid[h];
    #pragma unroll 8
    for (int i = 0; i < 64; i++) {
        fi = fmaf(sFI[i], gw_img[(h << 6) + i], fi);
        fl = fmaf(sFL[i], gw_lid[(h << 6) + i], fl);
    }
    fi = fmaxf(fi, 0.f);
    fl = fmaxf(fl, 0.f);

    float s = tanhf(fr + fi + fl);
    sPI[h] = s * uw[h];
    sPV[h] = s * vw[h];
    __syncthreads();
    if (h == 0) {
        float aI = ub[0], aV = vb[0];
        for (int i = 0; i < 64; i++) { aI += sPI[i]; aV += sPV[i]; }
        sW[0] = 1.f / (1.f + expf(-aI));
        sW[1] = 1.f / (1.f + expf(-aV));
    }
    __syncthreads();
    float wI = sW[0], wL = sW[1];

    float z = pts_cam[(b * N_ + idx) * 3 + 2];
    bool near = (z <= g_thr);
    float o1 = near ? sFL[h] : sFI[h];
    float o2 = near ? sFI[h] * wI : sFL[h] * wL;
    out[((b << 7) + h) * M_ + m]        = o1;
    out[((b << 7) + 64 + h) * M_ + m]   = o2;
}

// ------------------------- launch --------------------------------------------
extern "C" void kernel_launch(void* const* d_in, const int* in_sizes, int n_in,
                              void* d_out, int out_size) {
    const float* xyz     = (const float*)d_in[0];
    const float* pts_cam = (const float*)d_in[1];
    const float* FI      = (const float*)d_in[2];
    const float* w1 = (const float*)d_in[3];
    const float* s1 = (const float*)d_in[4];
    const float* b1 = (const float*)d_in[5];
    const float* w2 = (const float*)d_in[6];
    const float* s2 = (const float*)d_in[7];
    const float* b2 = (const float*)d_in[8];
    const float* w3 = (const float*)d_in[9];
    const float* s3 = (const float*)d_in[10];
    const float* b3 = (const float*)d_in[11];
    const float* tw1 = (const float*)d_in[12];
    const float* tb1 = (const float*)d_in[13];
    const float* tw2 = (const float*)d_in[14];
    const float* tb2 = (const float*)d_in[15];
    const float* tw3 = (const float*)d_in[16];
    const float* tb3 = (const float*)d_in[17];
    const float* gw_raw = (const float*)d_in[18];
    const float* gb_raw = (const float*)d_in[19];
    const float* gw_img = (const float*)d_in[20];
    const float* gb_img = (const float*)d_in[21];
    const float* gw_lid = (const float*)d_in[22];
    const float* gb_lid = (const float*)d_in[23];
    const float* uw = (const float*)d_in[24];
    const float* ub = (const float*)d_in[25];
    const float* vw = (const float*)d_in[26];
    const float* vb = (const float*)d_in[27];
    float* out = (float*)d_out;

    k_prep<<<(B_ * N_ + 255) / 256, 256>>>(xyz);
    k_thr<<<1, 64>>>(tw1, tb1, tw2, tb2, tw3, tb3);

    k_fps<<<B_ * G_, TCC>>>();

    k_knn<<<(B_ * M_) / 8, 256>>>(w1, s1, b1, w2, s2, b2, w3, s3, b3);
    k_fuse<<<B_ * M_, 64>>>(xyz, pts_cam, FI,
                            gw_raw, gb_raw, gw_img, gb_img, gw_lid, gb_lid,
                            uw, ub, vw, vb, out);
}

// round 12
// speedup vs baseline: 2.1187x; 1.1126x over previous
#include <cuda_runtime.h>
#include <math.h>

#define B_   2
#define N_   16384
#define M_   4096
#define KG_  32
#define FULL 0xffffffffu

#define TF   512                 // FPS threads
#define PPT  32                  // points per thread (contiguous sorted block)
#define NP2  16                  // f32x2 pairs per thread
#define NWF  (TF / 32)           // 16 warps

typedef unsigned long long ull;

// ------------------------- device scratch (no allocs) ------------------------
__device__ __align__(16) static float4 g_pk[B_][N_];   // orig order: x,y,z,|p|^2
__device__ __align__(16) static float4 g_sp[B_][N_];   // Morton order coords
__device__ static int   g_oid[B_][N_];                 // sorted pos -> orig idx
__device__ static int   g_fps[B_][M_];
__device__ static float g_FL[B_ * M_ * 64];
__device__ static float g_thr;

// ------------------------- f32x2 helpers -------------------------------------
__device__ __forceinline__ ull pack2(float a, float b) {
    ull r; asm("mov.b64 %0, {%1, %2};" : "=l"(r) : "f"(a), "f"(b)); return r;
}
__device__ __forceinline__ void unpack2(ull v, float& a, float& b) {
    asm("mov.b64 {%0, %1}, %2;" : "=f"(a), "=f"(b) : "l"(v));
}
__device__ __forceinline__ ull addx2(ull a, ull b) {
    ull r; asm("add.rn.f32x2 %0, %1, %2;" : "=l"(r) : "l"(a), "l"(b)); return r;
}
__device__ __forceinline__ ull mulx2(ull a, ull b) {
    ull r; asm("mul.rn.f32x2 %0, %1, %2;" : "=l"(r) : "l"(a), "l"(b)); return r;
}

// ------------------------- K1: prep (orig-order SoA + norms) -----------------
__global__ void k_prep(const float* __restrict__ xyz) {
    int i = blockIdx.x * blockDim.x + threadIdx.x;
    if (i >= B_ * N_) return;
    int b = i / N_, p = i - b * N_;
    float x = xyz[3 * i + 0], y = xyz[3 * i + 1], z = xyz[3 * i + 2];
    // matches jnp.sum(b*b,-1): ((x*x + y*y) + z*z), no fma contraction
    float n = __fadd_rn(__fadd_rn(__fmul_rn(x, x), __fmul_rn(y, y)), __fmul_rn(z, z));
    g_pk[b][p] = make_float4(x, y, z, n);
}

// ------------------------- K2: threshold net ---------------------------------
__global__ void k_thr(const float* __restrict__ tw1, const float* __restrict__ tb1,
                      const float* __restrict__ tw2, const float* __restrict__ tb2,
                      const float* __restrict__ tw3, const float* __restrict__ tb3) {
    __shared__ float t1s[64], t2s[64];
    int o = threadIdx.x;
    float dens = (float)(64.0 / (4.0 / 3.0 * 3.14159));   // radius 1.0
    t1s[o] = fmaxf(fmaf(dens, tw1[o], tb1[o]), 0.f);
    __syncthreads();
    float acc = tb2[o];
    #pragma unroll 8
    for (int i = 0; i < 64; i++) acc = fmaf(t1s[i], tw2[o * 64 + i], acc);
    t2s[o] = fmaxf(acc, 0.f);
    __syncthreads();
    if (o == 0) {
        float a = tb3[0];
        for (int i = 0; i < 64; i++) a = fmaf(t2s[i], tw3[i], a);
        float sg = 1.f / (1.f + expf(-a));
        g_thr = 20.f + 40.f * sg;
    }
}

// ------------------------- K_sort: Morton order (1 CTA per batch) ------------
__device__ __forceinline__ unsigned expand3(unsigned v) {
    v &= 0x3FFu;
    v = (v | (v << 16)) & 0x030000FFu;
    v = (v | (v << 8))  & 0x0300F00Fu;
    v = (v | (v << 4))  & 0x030C30C3u;
    v = (v | (v << 2))  & 0x09249249u;
    return v;
}
__global__ __launch_bounds__(1024, 1) void k_sort() {
    extern __shared__ ull skey[];                 // 16384 keys = 128KB
    __shared__ float rmn[3][32], rmx[3][32];
    __shared__ float bmn[3], bscale[3];
    int b = blockIdx.x, tid = threadIdx.x;
    int lane = tid & 31, wid = tid >> 5;

    float mn[3] = {1e30f, 1e30f, 1e30f}, mx[3] = {-1e30f, -1e30f, -1e30f};
    for (int i = tid; i < N_; i += 1024) {
        float4 p = g_pk[b][i];
        mn[0] = fminf(mn[0], p.x); mx[0] = fmaxf(mx[0], p.x);
        mn[1] = fminf(mn[1], p.y); mx[1] = fmaxf(mx[1], p.y);
        mn[2] = fminf(mn[2], p.z); mx[2] = fmaxf(mx[2], p.z);
    }
    #pragma unroll
    for (int s = 16; s; s >>= 1)
        #pragma unroll
        for (int d = 0; d < 3; d++) {
            mn[d] = fminf(mn[d], __shfl_xor_sync(FULL, mn[d], s));
            mx[d] = fmaxf(mx[d], __shfl_xor_sync(FULL, mx[d], s));
        }
    if (lane == 0)
        for (int d = 0; d < 3; d++) { rmn[d][wid] = mn[d]; rmx[d][wid] = mx[d]; }
    __syncthreads();
    if (tid == 0) {
        for (int d = 0; d < 3; d++) {
            float a = 1e30f, c = -1e30f;
            for (int w = 0; w < 32; w++) { a = fminf(a, rmn[d][w]); c = fmaxf(c, rmx[d][w]); }
            bmn[d] = a;
            bscale[d] = 1023.0f / fmaxf(c - a, 1e-9f);
        }
    }
    __syncthreads();

    for (int i = tid; i < N_; i += 1024) {
        float4 p = g_pk[b][i];
        int qx = min(1023, max(0, (int)((p.x - bmn[0]) * bscale[0])));
        int qy = min(1023, max(0, (int)((p.y - bmn[1]) * bscale[1])));
        int qz = min(1023, max(0, (int)((p.z - bmn[2]) * bscale[2])));
        unsigned mort = expand3((unsigned)qx) | (expand3((unsigned)qy) << 1)
                      | (expand3((unsigned)qz) << 2);
        skey[i] = ((ull)mort << 32) | (unsigned)i;
    }
    __syncthreads();

    // bitonic sort, ascending (keys unique: idx in low bits)
    for (unsigned k = 2; k <= N_; k <<= 1) {
        for (unsigned j = k >> 1; j > 0; j >>= 1) {
            for (unsigned i = tid; i < N_; i += 1024) {
                unsigned ixj = i ^ j;
                if (ixj > i) {
                    ull a = skey[i], c = skey[ixj];
                    bool up = ((i & k) == 0);
                    if ((a > c) == up) { skey[i] = c; skey[ixj] = a; }
                }
            }
            __syncthreads();
        }
    }

    for (int i = tid; i < N_; i += 1024) {
        int p = (int)(skey[i] & 0xFFFFFFFFull);
        g_sp[b][i] = g_pk[b][p];
        g_oid[b][i] = p;
    }
}

// ------------------------- K3: exact lazy FPS (1 CTA per batch) --------------
// Thread owns 32 sorted-CONTIGUOUS points (tight Morton ball: ctr, rad).
// Coords in SMEM pair-packed (conflict-free, LDS.64); dist[32] in registers;
// original ids as uint16 in SMEM. Prune is provably exact:
//   d2(c,ctr) >= (sqrt(bv)+rad)^2*1.0002  =>  every dist-min in group no-op.
// Argmax is two-phase & tie-exact: REDUX max value, then REDUX min
// (oid<<14|sidx) over all points whose dist bits equal the max — identical to
// jnp.argmax first-max-in-ORIGINAL-order semantics.
__global__ __launch_bounds__(TF, 1) void k_fps() {
    extern __shared__ char smx[];
    float* fx = (float*)smx;                       // N_ floats, pair-packed
    float* fy = fx + N_;
    float* fz = fy + N_;
    unsigned short* soid = (unsigned short*)(fz + N_);   // N_ uint16
    ull* ufx = (ull*)fx;
    ull* ufy = (ull*)fy;
    ull* ufz = (ull*)fz;
    __shared__ unsigned s_val[NWF], s_cand[NWF];
    __shared__ unsigned s_gmax, s_win;

    int b = blockIdx.x;
    int tid = threadIdx.x;
    int lane = tid & 31, wid = tid >> 5;

    // fill SMEM: sorted idx i = t*32 + k, pair j=k>>1, half h=k&1
    for (int i = tid; i < N_; i += TF) {
        float4 p = g_sp[b][i];
        int t = i >> 5, k = i & 31;
        int slot = (((k >> 1) * TF + t) << 1) | (k & 1);
        fx[slot] = p.x; fy[slot] = p.y; fz[slot] = p.z;
        soid[(k)*TF + t] = (unsigned short)g_oid[b][i];
    }
    __syncthreads();

    // per-thread bounding ball over its contiguous 32 points + dist init
    float dist[PPT];
    float mnx = 1e30f, mny = 1e30f, mnz = 1e30f;
    float mxx = -1e30f, mxy = -1e30f, mxz = -1e30f;
    #pragma unroll
    for (int j = 0; j < NP2; j++) {
        float x0, x1, y0, y1, z0, z1;
        unpack2(ufx[j * TF + tid], x0, x1);
        unpack2(ufy[j * TF + tid], y0, y1);
        unpack2(ufz[j * TF + tid], z0, z1);
        mnx = fminf(mnx, fminf(x0, x1)); mxx = fmaxf(mxx, fmaxf(x0, x1));
        mny = fminf(mny, fminf(y0, y1)); mxy = fmaxf(mxy, fmaxf(y0, y1));
        mnz = fminf(mnz, fminf(z0, z1)); mxz = fmaxf(mxz, fmaxf(z0, z1));
        dist[2 * j] = 1e10f; dist[2 * j + 1] = 1e10f;
    }
    float ctrx = 0.5f * (mnx + mxx);
    float ctry = 0.5f * (mny + mxy);
    float ctrz = 0.5f * (mnz + mxz);
    float maxd2 = 0.f;
    #pragma unroll
    for (int j = 0; j < NP2; j++) {
        float x0, x1, y0, y1, z0, z1;
        unpack2(ufx[j * TF + tid], x0, x1);
        unpack2(ufy[j * TF + tid], y0, y1);
        unpack2(ufz[j * TF + tid], z0, z1);
        float dx = x0 - ctrx, dy = y0 - ctry, dz = z0 - ctrz;
        maxd2 = fmaxf(maxd2, dx * dx + dy * dy + dz * dz);
        dx = x1 - ctrx; dy = y1 - ctry; dz = z1 - ctrz;
        maxd2 = fmaxf(maxd2, dx * dx + dy * dy + dz * dz);
    }
    float rad = sqrtf(maxd2) * 1.0002f + 1e-7f;

    float thr = 3.402823466e38f;           // force compute at it=0
    unsigned tvalbits = 0;

    float4 c0 = g_pk[b][0];                // first centroid = orig point 0
    float cx = c0.x, cy = c0.y, cz = c0.z;
    unsigned fwin = 0;

    for (int it = 0; it < M_; ++it) {
        if (tid == 0) g_fps[b][it] = (int)fwin;
        if (it == M_ - 1) break;

        float dxc = ctrx - cx, dyc = ctry - cy, dzc = ctrz - cz;
        float d2c = dxc * dxc + dyc * dyc + dzc * dzc;
        bool active = d2c < thr;
        if (__any_sync(FULL, active)) {
            ull ncx = pack2(-cx, -cx), ncy = pack2(-cy, -cy), ncz = pack2(-cz, -cz);
            float nbv = 0.f;
            #pragma unroll
            for (int j = 0; j < NP2; j++) {
                // x + (-c) == x - c exactly; ((dx*dx+dy*dy)+dz*dz) rn order
                ull dx = addx2(ufx[j * TF + tid], ncx);
                ull dy = addx2(ufy[j * TF + tid], ncy);
                ull dz = addx2(ufz[j * TF + tid], ncz);
                ull d2 = addx2(addx2(mulx2(dx, dx), mulx2(dy, dy)), mulx2(dz, dz));
                float d0, d1; unpack2(d2, d0, d1);
                float n0 = fminf(dist[2 * j], d0);     dist[2 * j] = n0;
                float n1 = fminf(dist[2 * j + 1], d1); dist[2 * j + 1] = n1;
                nbv = fmaxf(nbv, fmaxf(n0, n1));
            }
            float sb = sqrtf(nbv) + rad;
            thr = sb * sb * 1.0002f;
            tvalbits = __float_as_uint(nbv);   // nonneg: bits order-monotonic
        }
        // phase A: global max value
        unsigned wmax = __reduce_max_sync(FULL, tvalbits);
        if (lane == 0) s_val[wid] = wmax;
        __syncthreads();
        if (wid == 0) {
            unsigned v2 = (lane < NWF) ? s_val[lane] : 0u;
            unsigned g2 = __reduce_max_sync(FULL, v2);
            if (lane == 0) s_gmax = g2;
        }
        __syncthreads();
        unsigned gmax = s_gmax;
        // phase B: min ORIGINAL index among all points with dist bits == gmax
        unsigned cand = 0xffffffffu;
        if (tvalbits == gmax) {
            #pragma unroll
            for (int k = 0; k < PPT; k++) {
                if (__float_as_uint(dist[k]) == gmax) {
                    unsigned oid = soid[k * TF + tid];
                    unsigned key = (oid << 14) | (unsigned)(tid * 32 + k);
                    cand = min(cand, key);
                }
            }
        }
        unsigned wmin = __reduce_min_sync(FULL, cand);
        if (lane == 0) s_cand[wid] = wmin;
        __syncthreads();
        if (wid == 0) {
            unsigned c2 = (lane < NWF) ? s_cand[lane] : 0xffffffffu;
            unsigned m = __reduce_min_sync(FULL, c2);
            if (lane == 0) s_win = m;
        }
        __syncthreads();
        unsigned key = s_win;
        unsigned sidx = key & 0x3FFFu;
        fwin = key >> 14;
        int t2 = sidx >> 5, k2 = sidx & 31;
        int slot = (((k2 >> 1) * TF + t2) << 1) | (k2 & 1);
        cx = fx[slot]; cy = fy[slot]; cz = fz[slot];   // broadcast LDS
    }
}

// ------------------------- K4: kNN top-32 + shared MLP + masked max ----------
__global__ __launch_bounds__(256) void k_knn(
    const float* __restrict__ w1, const float* __restrict__ s1, const float* __restrict__ b1,
    const float* __restrict__ w2, const float* __restrict__ s2, const float* __restrict__ b2,
    const float* __restrict__ w3, const float* __restrict__ s3, const float* __restrict__ b3) {

    __shared__ float4 s_tile[2048];                       // 32 KB
    __shared__ float s_w1[96],  s_s1[32], s_b1[32];
    __shared__ float s_w2[1024], s_s2[32], s_b2[32];
    __shared__ float s_w3[2048], s_s3[64], s_b3[64];

    int tid = threadIdx.x;
    int lane = tid & 31, warp = tid >> 5;

    for (int i = tid; i < 96;   i += 256) s_w1[i] = w1[i];
    for (int i = tid; i < 1024; i += 256) s_w2[i] = w2[i];
    for (int i = tid; i < 2048; i += 256) s_w3[i] = w3[i];
    if (tid < 32) { s_s1[tid] = s1[tid]; s_b1[tid] = b1[tid];
                    s_s2[tid] = s2[tid]; s_b2[tid] = b2[tid]; }
    if (tid < 64) { s_s3[tid] = s3[tid]; s_b3[tid] = b3[tid]; }

    int b = blockIdx.x >> 9;                               // 512 blocks / batch
    int m = ((blockIdx.x & 511) << 3) + warp;
    int cidx = g_fps[b][m];
    float4 c = g_pk[b][cidx];

    const float INFP = __int_as_float(0x7f800000);
    float curmax = INFP;
    float candD  = INFP;
    int   candI  = 0x7fffff00 | lane;   // lane-unique sentinels while unfull

    for (int tile = 0; tile < 8; tile++) {
        __syncthreads();
        for (int i = tid; i < 2048; i += 256) s_tile[i] = g_pk[b][(tile << 11) + i];
        __syncthreads();
        for (int t = 0; t < 64; t++) {
            float4 p = s_tile[(t << 5) + lane];
            int pidx = (tile << 11) + (t << 5) + lane;
            // reference cdist: (an + bn) - 2*dot, no fma; clamp at 0
            float dot = __fadd_rn(__fadd_rn(__fmul_rn(c.x, p.x), __fmul_rn(c.y, p.y)),
                                  __fmul_rn(c.z, p.z));
            float d2 = fmaxf(__fsub_rn(__fadd_rn(c.w, p.w), __fmul_rn(2.f, dot)), 0.f);
            unsigned bal = __ballot_sync(FULL, d2 < curmax);
            while (bal) {
                int src = __ffs(bal) - 1;
                bal &= bal - 1;
                float dn = __shfl_sync(FULL, d2, src);
                int   in = __shfl_sync(FULL, pidx, src);
                if (dn < curmax) {               // strict < : stable top_k ties
                    unsigned db = __float_as_uint(candD);
                    unsigned mb = __reduce_max_sync(FULL, db);
                    int ei = (db == mb) ? candI : -1;
                    int me = __reduce_max_sync(FULL, ei);
                    if (db == mb && candI == me) { candD = dn; candI = in; }
                    curmax = __uint_as_float(
                        __reduce_max_sync(FULL, __float_as_uint(candD)));
                }
            }
        }
    }

    bool msk = (__fsqrt_rn(candD) <= 0.8f);
    float4 np = g_pk[b][candI];
    float gx = __fsub_rn(np.x, c.x);
    float gy = __fsub_rn(np.y, c.y);
    float gz = __fsub_rn(np.z, c.z);

    float h1[32];
    #pragma unroll
    for (int o = 0; o < 32; o++) {
        float a = __fmul_rn(gx, s_w1[3 * o]);
        a = fmaf(gy, s_w1[3 * o + 1], a);
        a = fmaf(gz, s_w1[3 * o + 2], a);
        h1[o] = fmaxf(fmaf(a, s_s1[o], s_b1[o]), 0.f);
    }
    float h2[32];
    #pragma unroll
    for (int o = 0; o < 32; o++) {
        float acc = 0.f;
        #pragma unroll
        for (int i = 0; i < 32; i++) acc = fmaf(h1[i], s_w2[(o << 5) + i], acc);
        h2[o] = fmaxf(fmaf(acc, s_s2[o], s_b2[o]), 0.f);
    }
    const float NINF = __int_as_float(0xff800000);
    float* outFL = &g_FL[((b << 12) + m) * 64];
    for (int o = 0; o < 64; o++) {
        float acc = 0.f;
        #pragma unroll
        for (int i = 0; i < 32; i++) acc = fmaf(h2[i], s_w3[(o << 5) + i], acc);
        float v = fmaxf(fmaf(acc, s_s3[o], s_b3[o]), 0.f);
        if (!msk) v = NINF;
        #pragma unroll
        for (int s = 16; s; s >>= 1) v = fmaxf(v, __shfl_xor_sync(FULL, v, s));
        if (lane == 0) outFL[o] = v;
    }
}

// ------------------------- K5: DAM fusion ------------------------------------
__global__ __launch_bounds__(64) void k_fuse(
    const float* __restrict__ xyz, const float* __restrict__ pts_cam,
    const float* __restrict__ FI,
    const float* __restrict__ gw_raw, const float* __restrict__ gb_raw,
    const float* __restrict__ gw_img, const float* __restrict__ gb_img,
    const float* __restrict__ gw_lid, const float* __restrict__ gb_lid,
    const float* __restrict__ uw, const float* __restrict__ ub,
    const float* __restrict__ vw, const float* __restrict__ vb,
    float* __restrict__ out) {

    __shared__ float sFI[64], sFL[64], sPI[64], sPV[64], sW[2];
    int h = threadIdx.x;
    int g = blockIdx.x;
    int b = g >> 12, m = g & 4095;
    int idx = g_fps[b][m];

    sFI[h] = FI[((b << 6) + h) * N_ + idx];
    sFL[h] = g_FL[((b << 12) + m) * 64 + h];
    __syncthreads();

    float x0 = xyz[(b * N_ + idx) * 3 + 0];
    float x1 = xyz[(b * N_ + idx) * 3 + 1];
    float x2 = xyz[(b * N_ + idx) * 3 + 2];

    float fr = gb_raw[h];
    fr = fmaf(x0, gw_raw[3 * h + 0], fr);
    fr = fmaf(x1, gw_raw[3 * h + 1], fr);
    fr = fmaf(x2, gw_raw[3 * h + 2], fr);
    fr = fmaxf(fr, 0.f);

    float fi = gb_img[h], fl = gb_lid[h];
    #pragma unroll 8
    for (int i = 0; i < 64; i++) {
        fi = fmaf(sFI[i], gw_img[(h << 6) + i], fi);
        fl = fmaf(sFL[i], gw_lid[(h << 6) + i], fl);
    }
    fi = fmaxf(fi, 0.f);
    fl = fmaxf(fl, 0.f);

    float s = tanhf(fr + fi + fl);
    sPI[h] = s * uw[h];
    sPV[h] = s * vw[h];
    __syncthreads();
    if (h == 0) {
        float aI = ub[0], aV = vb[0];
        for (int i = 0; i < 64; i++) { aI += sPI[i]; aV += sPV[i]; }
        sW[0] = 1.f / (1.f + expf(-aI));
        sW[1] = 1.f / (1.f + expf(-aV));
    }
    __syncthreads();
    float wI = sW[0], wL = sW[1];

    float z = pts_cam[(b * N_ + idx) * 3 + 2];
    bool near = (z <= g_thr);
    float o1 = near ? sFL[h] : sFI[h];
    float o2 = near ? sFI[h] * wI : sFL[h] * wL;
    out[((b << 7) + h) * M_ + m]        = o1;
    out[((b << 7) + 64 + h) * M_ + m]   = o2;
}

// ------------------------- launch --------------------------------------------
extern "C" void kernel_launch(void* const* d_in, const int* in_sizes, int n_in,
                              void* d_out, int out_size) {
    const float* xyz     = (const float*)d_in[0];
    const float* pts_cam = (const float*)d_in[1];
    const float* FI      = (const float*)d_in[2];
    const float* w1 = (const float*)d_in[3];
    const float* s1 = (const float*)d_in[4];
    const float* b1 = (const float*)d_in[5];
    const float* w2 = (const float*)d_in[6];
    const float* s2 = (const float*)d_in[7];
    const float* b2 = (const float*)d_in[8];
    const float* w3 = (const float*)d_in[9];
    const float* s3 = (const float*)d_in[10];
    const float* b3 = (const float*)d_in[11];
    const float* tw1 = (const float*)d_in[12];
    const float* tb1 = (const float*)d_in[13];
    const float* tw2 = (const float*)d_in[14];
    const float* tb2 = (const float*)d_in[15];
    const float* tw3 = (const float*)d_in[16];
    const float* tb3 = (const float*)d_in[17];
    const float* gw_raw = (const float*)d_in[18];
    const float* gb_raw = (const float*)d_in[19];
    const float* gw_img = (const float*)d_in[20];
    const float* gb_img = (const float*)d_in[21];
    const float* gw_lid = (const float*)d_in[22];
    const float* gb_lid = (const float*)d_in[23];
    const float* uw = (const float*)d_in[24];
    const float* ub = (const float*)d_in[25];
    const float* vw = (const float*)d_in[26];
    const float* vb = (const float*)d_in[27];
    float* out = (float*)d_out;

    k_prep<<<(B_ * N_ + 255) / 256, 256>>>(xyz);
    k_thr<<<1, 64>>>(tw1, tb1, tw2, tb2, tw3, tb3);

    cudaFuncSetAttribute(k_sort, cudaFuncAttributeMaxDynamicSharedMemorySize,
                         N_ * (int)sizeof(ull));
    k_sort<<<B_, 1024, N_ * sizeof(ull)>>>();

    int fps_smem = 3 * N_ * (int)sizeof(float) + N_ * (int)sizeof(unsigned short);
    cudaFuncSetAttribute(k_fps, cudaFuncAttributeMaxDynamicSharedMemorySize, fps_smem);
    k_fps<<<B_, TF, fps_smem>>>();

    k_knn<<<(B_ * M_) / 8, 256>>>(w1, s1, b1, w2, s2, b2, w3, s3, b3);
    k_fuse<<<B_ * M_, 64>>>(xyz, pts_cam, FI,
                            gw_raw, gb_raw, gw_img, gb_img, gw_lid, gb_lid,
                            uw, ub, vw, vb, out);
}